// round 17
// baseline (speedup 1.0000x reference)
#include <cuda_runtime.h>

#define EPSV2      1e-8f       // EPSV^2
#define TOLSQ      1e-8f       // (1e-4)^2 rotation threshold (validated)
#define TOLSQ_FLAG 9e-8f       // (3e-4)^2 sweep-continuation threshold
#define MAXSWEEP   18
#define FULLM      0xffffffffu

typedef unsigned long long u64;

// ---- packed f32x2 helpers (sm_10x; ptxas never emits these from C++) ----
__device__ __forceinline__ u64 mul2(u64 a, u64 b) {
    u64 r; asm("mul.rn.f32x2 %0, %1, %2;" : "=l"(r) : "l"(a), "l"(b)); return r;
}
__device__ __forceinline__ u64 fma2(u64 a, u64 b, u64 c) {
    u64 r; asm("fma.rn.f32x2 %0, %1, %2, %3;" : "=l"(r) : "l"(a), "l"(b), "l"(c)); return r;
}
__device__ __forceinline__ u64 pack2(float lo, float hi) {
    u64 r; asm("mov.b64 %0, {%1, %2};" : "=l"(r) : "f"(lo), "f"(hi)); return r;
}
__device__ __forceinline__ float hadd2(u64 a) {
    float lo, hi; asm("mov.b64 {%0, %1}, %2;" : "=f"(lo), "=f"(hi) : "l"(a));
    return lo + hi;
}

// One CTA per 64x64 SPD matrix. One-sided Jacobi, register-resident packed
// columns, hierarchical tournament. R17 (vs R15):
//  (a) the 4th inner rotate-B is FOLDED into the ring-staging addressing for
//      outers 1..14 (B-half written to slot (team+3)&3 instead of physically
//      rotating registers back to home) — saves 8 SHFL.32 per outer. Outer 0
//      keeps the rotation so the intra-half block sees home layout.
//      Pairings/values are bit-identical -> rel_err must not change.
//  (b) __launch_bounds__(256,6): reg cap ~40 (inner live set audited ~38-40),
//      occupancy 61% -> ~73% to eat the issue-stall slack.
// (redux.sync.add.f32 does NOT exist on sm_103 — R16; shfl butterfly stays.)
__global__ void __launch_bounds__(256, 6)
logm_jacobi_kernel(const float* __restrict__ in, float* __restrict__ out)
{
    __shared__ __align__(16) float SH[8192];   // staging; epilogue U matrix
    __shared__ float wlog[64];
    __shared__ int   s_flag;

    const int tid  = threadIdx.x;
    const int lane = tid & 31;
    const int warp = tid >> 5;
    const int team = lane >> 3;               // 4 teams per warp
    const int sl   = lane & 7;                // lane within team
    const unsigned tm = 0xffu << (team << 3); // team shfl mask
    const size_t base = (size_t)blockIdx.x * 4096;

    // pair visit: 3 packed dots (independent chains) + butterfly + rotation
#define VISIT(TT, BB)                                                        \
    {                                                                        \
        u64 dpq2 = mul2(TT[0], BB[0]);                                       \
        u64 dpp2 = mul2(TT[0], TT[0]);                                       \
        u64 dqq2 = mul2(BB[0], BB[0]);                                       \
        _Pragma("unroll")                                                    \
        for (int i = 1; i < 4; ++i) {                                        \
            dpq2 = fma2(TT[i], BB[i], dpq2);                                 \
            dpp2 = fma2(TT[i], TT[i], dpp2);                                 \
            dqq2 = fma2(BB[i], BB[i], dqq2);                                 \
        }                                                                    \
        float dpq = hadd2(dpq2);                                             \
        float dpp = hadd2(dpp2);                                             \
        float dqq = hadd2(dqq2);                                             \
        _Pragma("unroll")                                                    \
        for (int o = 4; o; o >>= 1) {                                        \
            dpq += __shfl_xor_sync(tm, dpq, o);                              \
            dpp += __shfl_xor_sync(tm, dpp, o);                              \
            dqq += __shfl_xor_sync(tm, dqq, o);                              \
        }                                                                    \
        float dsq = dpq * dpq;                                               \
        float rel = dpp * dqq;                                               \
        if (dsq > TOLSQ * rel) {                                             \
            float tau = __fdividef(dqq - dpp, 2.0f * dpq);                   \
            float t = copysignf(1.0f, tau) /                                 \
                      (fabsf(tau) + sqrtf(1.0f + tau * tau));                \
            float c = rsqrtf(1.0f + t * t);                                  \
            float s = t * c;                                                 \
            u64 c2  = pack2(c, c);                                           \
            u64 s2  = pack2(s, s);                                           \
            u64 ms2 = pack2(-s, -s);                                         \
            _Pragma("unroll")                                                \
            for (int i = 0; i < 4; ++i) {                                    \
                u64 tp = fma2(ms2, BB[i], mul2(c2, TT[i]));                  \
                BB[i]  = fma2(s2,  TT[i], mul2(c2, BB[i]));                  \
                TT[i]  = tp;                                                 \
            }                                                                \
            if (sl == 0 && dsq > TOLSQ_FLAG * rel) s_flag = 1;               \
        }                                                                    \
    }

    // ---- load: warp w team t holds cols 4w+t (T) and 32+4w+t (B) ----
    u64 T[4], B[4];
    {
        const int c = warp * 4 + team;
        const ulonglong2* gt = reinterpret_cast<const ulonglong2*>(in + base + c * 64 + sl * 8);
        const ulonglong2* gb = reinterpret_cast<const ulonglong2*>(in + base + (32 + c) * 64 + sl * 8);
        ulonglong2 t0 = gt[0], t1 = gt[1], b0 = gb[0], b1 = gb[1];
        T[0]=t0.x; T[1]=t0.y; T[2]=t1.x; T[3]=t1.y;
        B[0]=b0.x; B[1]=b0.y; B[2]=b1.x; B[3]=b1.y;
    }

    const int rotsrc = (lane + 8) & 31;       // +1-team rotation source

    for (int sweep = 0; sweep < MAXSWEEP; ++sweep) {
        if (tid == 0) s_flag = 0;
        __syncthreads();

        for (int outer = 0; outer < 15; ++outer) {
            // ---- 4 inner cross rounds (intra-warp only). The 4th rotation
            //      (pure home-restore) is skipped for outer>0; the staging
            //      addressing below compensates. Condition is warp-uniform.
            #pragma unroll
            for (int rho = 0; rho < 4; ++rho) {
                VISIT(T, B);
                if (rho < 3 || outer == 0) {
                    #pragma unroll
                    for (int i = 0; i < 4; ++i)      // rotate B one team
                        B[i] = __shfl_sync(FULLM, B[i], rotsrc);
                }
            }

            // ---- intra-half pairs, once per sweep (B is home here) ----
            if (outer == 0) {
                // gather: t0:(tc0,tc1) t1:(tc2,tc3) t2:(bc0,bc1) t3:(bc2,bc3)
                const int sTA = (team == 1) ? rotsrc : lane;
                const int sBA = (team == 2) ? ((lane + 16) & 31) : ((lane + 24) & 31);
                const int sTB = (team == 0) ? rotsrc : ((lane + 16) & 31);
                const int sBB = (team == 2) ? ((lane + 24) & 31) : lane;
                #pragma unroll
                for (int i = 0; i < 4; ++i) {
                    u64 tA = __shfl_sync(FULLM, T[i], sTA);
                    u64 bA = __shfl_sync(FULLM, B[i], sBA);
                    u64 tB = __shfl_sync(FULLM, T[i], sTB);
                    u64 bB = __shfl_sync(FULLM, B[i], sBB);
                    T[i] = (team < 2) ? tA : bA;
                    B[i] = (team < 2) ? tB : bB;
                }
                VISIT(T, B);
                {   // swap1: even.B <-> odd.T (xor 8)
                    const bool ev = ((team & 1) == 0);
                    #pragma unroll
                    for (int i = 0; i < 4; ++i) {
                        u64 tx = __shfl_xor_sync(FULLM, T[i], 8);
                        u64 bx = __shfl_xor_sync(FULLM, B[i], 8);
                        u64 nB = ev ? tx : B[i];
                        u64 nT = ev ? T[i] : bx;
                        T[i] = nT; B[i] = nB;
                    }
                }
                VISIT(T, B);
                #pragma unroll
                for (int i = 0; i < 4; ++i)      // swap2: B <-> B (xor 8)
                    B[i] = __shfl_xor_sync(FULLM, B[i], 8);
                VISIT(T, B);
                // restore home: t:(tc_t, bc_t)
                const int rT = (team == 2) ? ((lane + 24) & 31) : rotsrc;
                const int rB = (team == 2) ? rotsrc : ((lane + 24) & 31);
                const int r16 = (lane + 16) & 31;
                #pragma unroll
                for (int i = 0; i < 4; ++i) {
                    u64 rb  = __shfl_sync(FULLM, B[i], rT);
                    u64 rt  = __shfl_sync(FULLM, T[i], r16);
                    u64 rb2 = __shfl_sync(FULLM, B[i], rB);
                    T[i] = (team < 2) ? T[i] : rb;
                    B[i] = (team < 2) ? rt   : rb2;
                }
            }

            // ---- outer rotation: half-blocks through the ring via staging.
            //      T registers are always home. B registers hold bc_{team+3}
            //      when outer>0 (skipped 4th rotation) -> write them to slot
            //      (team+3)&3; reads stay home-addressed.
            u64* st  = reinterpret_cast<u64*>(SH) + (outer & 1) * 2048;
            u64* stT = st;                         // [warp][128] u64
            u64* stB = st + 1024;
            const int off  = team * 32 + sl * 4;   // u64 units (home)
            const int bslot = (outer == 0) ? team : ((team + 3) & 3);
            const int boff = bslot * 32 + sl * 4;
            if (warp >= 1 && warp <= 6) {          // TH -> warp+1
                ulonglong2* d = reinterpret_cast<ulonglong2*>(stT + (warp + 1) * 128 + off);
                d[0] = make_ulonglong2(T[0], T[1]);
                d[1] = make_ulonglong2(T[2], T[3]);
            }
            if (warp == 0) {                       // BH_0 -> warp1's TH
                ulonglong2* d = reinterpret_cast<ulonglong2*>(stT + 1 * 128 + boff);
                d[0] = make_ulonglong2(B[0], B[1]);
                d[1] = make_ulonglong2(B[2], B[3]);
            }
            if (warp >= 1) {                       // BH -> warp-1
                ulonglong2* d = reinterpret_cast<ulonglong2*>(stB + (warp - 1) * 128 + boff);
                d[0] = make_ulonglong2(B[0], B[1]);
                d[1] = make_ulonglong2(B[2], B[3]);
            }
            if (warp == 7) {                       // TH_7 -> own BH (T is home)
                #pragma unroll
                for (int i = 0; i < 4; ++i) B[i] = T[i];
            }
            __syncthreads();
            if (warp >= 1) {                       // receive TH (home layout)
                const ulonglong2* s4 = reinterpret_cast<const ulonglong2*>(stT + warp * 128 + off);
                ulonglong2 a = s4[0], b = s4[1];
                T[0]=a.x; T[1]=a.y; T[2]=b.x; T[3]=b.y;
            }
            if (warp <= 6) {                       // receive BH (home layout)
                const ulonglong2* s4 = reinterpret_cast<const ulonglong2*>(stB + warp * 128 + off);
                ulonglong2 a = s4[0], b = s4[1];
                B[0]=a.x; B[1]=a.y; B[2]=b.x; B[3]=b.y;
            }
        }

        int active = s_flag;
        __syncthreads();
        if (!active) break;
    }

    // ---- norms -> eigenvalues; normalized columns -> SH (order-free) ----
    {
        const int k = warp * 4 + team;
        u64 dpp2 = mul2(T[0], T[0]);
        u64 dqq2 = mul2(B[0], B[0]);
        #pragma unroll
        for (int i = 1; i < 4; ++i) {
            dpp2 = fma2(T[i], T[i], dpp2);
            dqq2 = fma2(B[i], B[i], dqq2);
        }
        float dpp = hadd2(dpp2);
        float dqq = hadd2(dqq2);
        #pragma unroll
        for (int o = 4; o; o >>= 1) {
            dpp += __shfl_xor_sync(tm, dpp, o);
            dqq += __shfl_xor_sync(tm, dqq, o);
        }
        float it = (dpp > 1e-30f) ? rsqrtf(dpp) : 0.0f;
        float ib = (dqq > 1e-30f) ? rsqrtf(dqq) : 0.0f;
        u64 it2 = pack2(it, it), ib2 = pack2(ib, ib);
        ulonglong2* mt = reinterpret_cast<ulonglong2*>(SH + (2 * k) * 64 + sl * 8);
        ulonglong2* mb = reinterpret_cast<ulonglong2*>(SH + (2 * k + 1) * 64 + sl * 8);
        mt[0] = make_ulonglong2(mul2(it2, T[0]), mul2(it2, T[1]));
        mt[1] = make_ulonglong2(mul2(it2, T[2]), mul2(it2, T[3]));
        mb[0] = make_ulonglong2(mul2(ib2, B[0]), mul2(ib2, B[1]));
        mb[1] = make_ulonglong2(mul2(ib2, B[2]), mul2(ib2, B[3]));
        if (sl == 0) {
            wlog[2 * k]     = 0.5f * logf(fmaxf(dpp, EPSV2));
            wlog[2 * k + 1] = 0.5f * logf(fmaxf(dqq, EPSV2));
        }
    }
    __syncthreads();

    // ---- O = U diag(w) U^T, 4x4 register tile per thread ----
    const int ta = tid >> 4;
    const int tb = tid & 15;
    float acc[4][4];
    #pragma unroll
    for (int i = 0; i < 4; ++i)
        #pragma unroll
        for (int j = 0; j < 4; ++j) acc[i][j] = 0.0f;

    for (int kk = 0; kk < 64; ++kk) {
        float w = wlog[kk];
        float4 ur = *reinterpret_cast<const float4*>(SH + kk * 64 + 4 * ta);
        float4 uc = *reinterpret_cast<const float4*>(SH + kk * 64 + 4 * tb);
        float r0 = w * ur.x, r1 = w * ur.y, r2 = w * ur.z, r3 = w * ur.w;
        acc[0][0] += r0 * uc.x; acc[0][1] += r0 * uc.y; acc[0][2] += r0 * uc.z; acc[0][3] += r0 * uc.w;
        acc[1][0] += r1 * uc.x; acc[1][1] += r1 * uc.y; acc[1][2] += r1 * uc.z; acc[1][3] += r1 * uc.w;
        acc[2][0] += r2 * uc.x; acc[2][1] += r2 * uc.y; acc[2][2] += r2 * uc.z; acc[2][3] += r2 * uc.w;
        acc[3][0] += r3 * uc.x; acc[3][1] += r3 * uc.y; acc[3][2] += r3 * uc.z; acc[3][3] += r3 * uc.w;
    }

    float* go = out + base;
    #pragma unroll
    for (int i = 0; i < 4; ++i) {
        float4 v = make_float4(acc[i][0], acc[i][1], acc[i][2], acc[i][3]);
        *reinterpret_cast<float4*>(go + (4 * ta + i) * 64 + 4 * tb) = v;
    }
#undef VISIT
}

extern "C" void kernel_launch(void* const* d_in, const int* in_sizes, int n_in,
                              void* d_out, int out_size)
{
    const float* x = (const float*)d_in[0];
    float* out = (float*)d_out;
    int batches = in_sizes[0] / 4096;
    logm_jacobi_kernel<<<batches, 256>>>(x, out);
}